// round 15
// baseline (speedup 1.0000x reference)
#include <cuda_runtime.h>
#include <cuda_bf16.h>
#include <cstdint>

// ---------------------------------------------------------------------------
// Problem constants
// ---------------------------------------------------------------------------
#define BATCH   4
#define TLEN    2048
#define BT      8192
#define GDIM    4
#define HID     1024
#define NHEADS  16
#define DHEAD   64
#define EMB     1024
#define CCH     4096
#define KS      4
#define DIL     3

// ---------------------------------------------------------------------------
// Compile-time per-head vocab offsets (prime search; mirrors reference)
// ---------------------------------------------------------------------------
constexpr bool c_isprime(long long n) {
    if (n < 2) return false;
    if (n % 2 == 0) return n == 2;
    for (long long i = 3; i * i <= n; i += 2)
        if (n % i == 0) return false;
    return true;
}
struct OffT { long long off[16]; };
constexpr OffT make_off() {
    long long sizes[16] = {};
    int idx = 0;
    for (int ng = 0; ng < 2; ng++) {
        long long start = 129280 - 1;
        for (int h = 0; h < 8; h++) {
            long long c = start + 1;
            for (;;) {
                bool ok = c_isprime(c);
                if (ok) for (int j = 0; j < idx; j++) if (sizes[j] == c) { ok = false; break; }
                if (ok) break;
                ++c;
            }
            sizes[idx++] = c;
            start = c;
        }
    }
    OffT o{};
    long long acc = 0;
    for (int i = 0; i < 16; i++) { o.off[i] = acc; acc += sizes[i]; }
    return o;
}
constexpr OffT HOFF = make_off();
__constant__ long long d_off[16] = {
    HOFF.off[0], HOFF.off[1], HOFF.off[2], HOFF.off[3],
    HOFF.off[4], HOFF.off[5], HOFF.off[6], HOFF.off[7],
    HOFF.off[8], HOFF.off[9], HOFF.off[10], HOFF.off[11],
    HOFF.off[12], HOFF.off[13], HOFF.off[14], HOFF.off[15]
};

// ---------------------------------------------------------------------------
// Scratch (device globals)
// ---------------------------------------------------------------------------
__device__ float g_A    [(size_t)BT * EMB];      //  32 MB (tf32-rounded embs)
__device__ float g_value[(size_t)BT * EMB];      //  32 MB
__device__ float g_keys [(size_t)BT * CCH];      // 128 MB
__device__ float g_vwt  [(size_t)EMB * HID];     //   4 MB
__device__ float g_kwt  [(size_t)CCH * HID];     //  16 MB

// ---------------------------------------------------------------------------
// PTX helpers
// ---------------------------------------------------------------------------
__device__ __forceinline__ uint32_t smem_u32(const void* p) {
    uint32_t a;
    asm("{ .reg .u64 t; cvta.to.shared.u64 t, %1; cvt.u32.u64 %0, t; }" : "=r"(a) : "l"(p));
    return a;
}

__device__ __forceinline__ float to_tf32(float x) {
    uint32_t r;
    asm("cvt.rna.tf32.f32 %0, %1;" : "=r"(r) : "f"(x));
    return __uint_as_float(r);
}

#define CP16(sm, gm) asm volatile("cp.async.cg.shared.global [%0], [%1], 16;" :: "r"(sm), "l"(gm))
#define CPCOMMIT()   asm volatile("cp.async.commit_group;" ::: "memory")
#define CPWAIT(n)    asm volatile("cp.async.wait_group %0;" :: "n"(n) : "memory")

#define LDSM4(r0, r1, r2, r3, a)                                           \
    asm volatile("ldmatrix.sync.aligned.m8n8.x4.shared.b16 {%0,%1,%2,%3}, [%4];" \
        : "=r"(r0), "=r"(r1), "=r"(r2), "=r"(r3) : "r"(a))

#define MMA1688(d, a, b0, b1)                                              \
    asm volatile("mma.sync.aligned.m16n8k8.row.col.f32.tf32.tf32.f32 "     \
        "{%0,%1,%2,%3}, {%4,%5,%6,%7}, {%8,%9}, {%0,%1,%2,%3};"            \
        : "+f"((d)[0]), "+f"((d)[1]), "+f"((d)[2]), "+f"((d)[3])           \
        : "r"((a)[0]), "r"((a)[1]), "r"((a)[2]), "r"((a)[3]),              \
          "r"(b0), "r"(b1))

// Swizzle for 128B rows (8 x 16B chunks): byte = row*128 + ((ch ^ (row&7))*16)
__device__ __forceinline__ uint32_t sofs32(int row, int ch) {
    return (uint32_t)(row * 128 + ((ch ^ (row & 7)) << 4));
}

#define TFB_A     16384               // A: 128 rows x 128B
#define TFB_B     32768               // B: 256 rows x 128B
#define TFB_BUF   (TFB_A + TFB_B)     // 48 KB per stage
#define STAGES    4
#define TFB_SMEM  (STAGES * TFB_BUF)  // 192 KB

// ---------------------------------------------------------------------------
// Single-pass TF32 NT GEMM, fat tiles + 4-stage cp.async ring:
//   C[m,n] = sum_k A[m,k]*B[n,k] + bias[n]   (K = 1024)
//   Block tile 128x256, 8 warps (2x4), warp tile 64x64, BK=32, 1 CTA/SM.
// ---------------------------------------------------------------------------
__global__ __launch_bounds__(256, 1)
void gemm_tf32(const float* __restrict__ A, const float* __restrict__ B,
               const float* __restrict__ bias, float* __restrict__ C, int ldc) {
    extern __shared__ __align__(128) char smem[];
    const uint32_t sb = smem_u32(smem);

    const int tid = threadIdx.x;
    const int lane = tid & 31, wid = tid >> 5;
    const int wm = wid >> 2, wn = wid & 3;            // warp grid 2x4
    const int bm = blockIdx.y * 128, bn = blockIdx.x * 256;

    const int lrow = tid >> 1;                        // 0..127
    const int lch0 = (tid & 1) * 4;                   // chunk half

    float acc[4][8][4];
    #pragma unroll
    for (int i = 0; i < 4; i++)
        #pragma unroll
        for (int j = 0; j < 8; j++)
            #pragma unroll
            for (int q = 0; q < 4; q++) acc[i][j][q] = 0.f;

    auto issue = [&](int kc, int buf) {
        uint32_t base = sb + buf * TFB_BUF;
        const float* ga = A + (size_t)(bm + lrow) * 1024 + kc * 32;
        #pragma unroll
        for (int i = 0; i < 4; i++) {
            int ch = lch0 + i;
            CP16(base + sofs32(lrow, ch), ga + ch * 4);
        }
        #pragma unroll
        for (int r2 = 0; r2 < 2; r2++) {
            int brow = lrow + r2 * 128;
            const float* gb = B + (size_t)(bn + brow) * 1024 + kc * 32;
            #pragma unroll
            for (int i = 0; i < 4; i++) {
                int ch = lch0 + i;
                CP16(base + TFB_A + sofs32(brow, ch), gb + ch * 4);
            }
        }
        CPCOMMIT();
    };

    // preload 3 stages
    issue(0, 0);
    issue(1, 1);
    issue(2, 2);

    for (int kc = 0; kc < 32; kc++) {
        int buf = kc & (STAGES - 1);
        CPWAIT(2);            // chunk kc complete (2 younger groups may remain)
        __syncthreads();      // all warps' chunk-kc data visible; also protects
                              // the buffer written below (consumed at iter kc-1)
        if (kc + 3 < 32) issue(kc + 3, (kc + 3) & (STAGES - 1));
        else             CPCOMMIT();   // keep group counting exact at the tail

        uint32_t baseA = sb + buf * TFB_BUF;
        uint32_t baseB = baseA + TFB_A;

        #pragma unroll
        for (int ks = 0; ks < 4; ks++) {
            // A fragments (m16k8 x4 tiles)
            const int arow_l = wm * 64 + (lane & 7) + ((lane >> 3) & 1) * 8;
            const int ach = ks * 2 + (lane >> 4);
            uint32_t af[4][4];
            #pragma unroll
            for (int mi = 0; mi < 4; mi++)
                LDSM4(af[mi][0], af[mi][1], af[mi][2], af[mi][3],
                      baseA + sofs32(arow_l + mi * 16, ach));

            // B fragments: one LDSM4 covers two n8k8 tiles
            const int brow_l = wn * 64 + (lane & 7) + ((lane >> 4) & 1) * 8;
            const int bch = ks * 2 + ((lane >> 3) & 1);
            uint32_t bf[8][2];
            #pragma unroll
            for (int p = 0; p < 4; p++)
                LDSM4(bf[2 * p][0], bf[2 * p][1], bf[2 * p + 1][0], bf[2 * p + 1][1],
                      baseB + sofs32(brow_l + p * 16, bch));

            #pragma unroll
            for (int mi = 0; mi < 4; mi++)
                #pragma unroll
                for (int nj = 0; nj < 8; nj++)
                    MMA1688(acc[mi][nj], af[mi], bf[nj][0], bf[nj][1]);
        }
    }

    __syncthreads();

    // epilogue: m16n8 fragment: c0=(r,c) c1=(r,c+1) c2=(r+8,c) c3=(r+8,c+1)
    #pragma unroll
    for (int mi = 0; mi < 4; mi++) {
        int r0 = bm + wm * 64 + mi * 16 + (lane >> 2);
        #pragma unroll
        for (int nj = 0; nj < 8; nj++) {
            int c = bn + wn * 64 + nj * 8 + (lane & 3) * 2;
            float2 bv = *(const float2*)&bias[c];
            float2 o0, o1;
            o0.x = acc[mi][nj][0] + bv.x;
            o0.y = acc[mi][nj][1] + bv.y;
            o1.x = acc[mi][nj][2] + bv.x;
            o1.y = acc[mi][nj][3] + bv.y;
            *(float2*)&C[(size_t)r0 * ldc + c]       = o0;
            *(float2*)&C[(size_t)(r0 + 8) * ldc + c] = o1;
        }
    }
}

// ---------------------------------------------------------------------------
// Embedding gather, tf32-rounded (grid=BT, block=256)
// ---------------------------------------------------------------------------
__global__ void gather_k(const int* __restrict__ hash,
                         const float* __restrict__ tab,
                         float* __restrict__ A) {
    int bt = blockIdx.x;
    int tid = threadIdx.x;
    int h = tid >> 4;
    int q = tid & 15;
    long long row = (long long)hash[(size_t)bt * NHEADS + h] + d_off[h];
    float4 v = *(const float4*)&tab[row * DHEAD + q * 4];
    float4 o;
    o.x = to_tf32(v.x); o.y = to_tf32(v.y);
    o.z = to_tf32(v.z); o.w = to_tf32(v.w);
    *(float4*)&A[(size_t)bt * EMB + h * DHEAD + q * 4] = o;
}

// ---------------------------------------------------------------------------
// Weight tf32 rounding
// ---------------------------------------------------------------------------
__global__ void wround_k(const float* __restrict__ w, float* __restrict__ o4, int n4) {
    int i = blockIdx.x * blockDim.x + threadIdx.x;
    if (i >= n4) return;
    float4 v = ((const float4*)w)[i];
    float4 o;
    o.x = to_tf32(v.x); o.y = to_tf32(v.y);
    o.z = to_tf32(v.z); o.w = to_tf32(v.w);
    ((float4*)o4)[i] = o;
}

// ---------------------------------------------------------------------------
// Reductions
// ---------------------------------------------------------------------------
__device__ __forceinline__ void block_reduce4(float v[4]) {
    #pragma unroll
    for (int o = 16; o; o >>= 1)
        #pragma unroll
        for (int q = 0; q < 4; q++) v[q] += __shfl_xor_sync(0xffffffffu, v[q], o);
    __shared__ float s[8][4];
    int w = threadIdx.x >> 5, l = threadIdx.x & 31;
    if (l == 0) { s[w][0] = v[0]; s[w][1] = v[1]; s[w][2] = v[2]; s[w][3] = v[3]; }
    __syncthreads();
    if (w == 0) {
        #pragma unroll
        for (int q = 0; q < 4; q++) v[q] = (l < 8) ? s[l][q] : 0.f;
        #pragma unroll
        for (int o = 4; o; o >>= 1)
            #pragma unroll
            for (int q = 0; q < 4; q++) v[q] += __shfl_xor_sync(0xffffffffu, v[q], o);
        if (l == 0) { s[0][0] = v[0]; s[0][1] = v[1]; s[0][2] = v[2]; s[0][3] = v[3]; }
    }
    __syncthreads();
    v[0] = s[0][0]; v[1] = s[0][1]; v[2] = s[0][2]; v[3] = s[0][3];
}

__device__ __forceinline__ float3 block_reduce3(float a, float b, float c) {
    #pragma unroll
    for (int o = 16; o; o >>= 1) {
        a += __shfl_xor_sync(0xffffffffu, a, o);
        b += __shfl_xor_sync(0xffffffffu, b, o);
        c += __shfl_xor_sync(0xffffffffu, c, o);
    }
    __shared__ float sa[8], sb[8], sc[8];
    int w = threadIdx.x >> 5, l = threadIdx.x & 31;
    if (l == 0) { sa[w] = a; sb[w] = b; sc[w] = c; }
    __syncthreads();
    if (w == 0) {
        a = (l < 8) ? sa[l] : 0.f;
        b = (l < 8) ? sb[l] : 0.f;
        c = (l < 8) ? sc[l] : 0.f;
        #pragma unroll
        for (int o = 4; o; o >>= 1) {
            a += __shfl_xor_sync(0xffffffffu, a, o);
            b += __shfl_xor_sync(0xffffffffu, b, o);
            c += __shfl_xor_sync(0xffffffffu, c, o);
        }
        if (l == 0) { sa[0] = a; sb[0] = b; sc[0] = c; }
    }
    __syncthreads();
    return make_float3(sa[0], sb[0], sc[0]);
}

// ---------------------------------------------------------------------------
// Final fused kernel: rms(hidden) on the fly -> conv -> silu -> q-rms ;
// k-rms ; gate ; out.  grid = BT*GDIM, block = 256.
// ---------------------------------------------------------------------------
__global__ void final_k(const float* __restrict__ hidden,
                        const float* __restrict__ scw,
                        const float* __restrict__ convw,
                        const float* __restrict__ keys,
                        const float* __restrict__ value,
                        const float* __restrict__ n1w,
                        const float* __restrict__ n2w,
                        float* __restrict__ out) {
    int r = blockIdx.x;
    int g = r & 3;
    int bt = r >> 2;
    int t = bt & (TLEN - 1);
    int tid = threadIdx.x;
    int d = tid * 4;

    float4 hx[KS];
    float ss[KS];
    #pragma unroll
    for (int k = 0; k < KS; k++) {
        int tp = t - (KS - 1 - k) * DIL;
        if (tp >= 0) {
            size_t row = ((size_t)(bt - (KS - 1 - k) * DIL) * GDIM + g);
            hx[k] = *(const float4*)&hidden[row * HID + d];
        } else {
            hx[k] = make_float4(0.f, 0.f, 0.f, 0.f);
        }
        ss[k] = hx[k].x*hx[k].x + hx[k].y*hx[k].y + hx[k].z*hx[k].z + hx[k].w*hx[k].w;
    }
    block_reduce4(ss);
    float rs[KS];
    #pragma unroll
    for (int k = 0; k < KS; k++)
        rs[k] = rsqrtf(ss[k] * (1.f / HID) + 1e-5f);

    const float4* wb = (const float4*)(convw + (size_t)(g * HID + d) * KS);
    float4 w0 = wb[0], w1 = wb[1], w2 = wb[2], w3 = wb[3];
    float4 sw = *(const float4*)&scw[(size_t)g * HID + d];

    float y0 = 0.f, y1 = 0.f, y2 = 0.f, y3 = 0.f;
    #pragma unroll
    for (int k = 0; k < KS; k++) {
        float rsk = rs[k];
        y0 = fmaf(hx[k].x * rsk, ((const float*)&w0)[k], y0);
        y1 = fmaf(hx[k].y * rsk, ((const float*)&w1)[k], y1);
        y2 = fmaf(hx[k].z * rsk, ((const float*)&w2)[k], y2);
        y3 = fmaf(hx[k].w * rsk, ((const float*)&w3)[k], y3);
    }
    y0 *= sw.x; y1 *= sw.y; y2 *= sw.z; y3 *= sw.w;

    float s0 = y0 / (1.f + __expf(-y0));
    float s1 = y1 / (1.f + __expf(-y1));
    float s2 = y2 / (1.f + __expf(-y2));
    float s3 = y3 / (1.f + __expf(-y3));

    float4 kv = *(const float4*)&keys[(size_t)bt * CCH + g * HID + d];
    float4 n1 = *(const float4*)&n1w[(size_t)g * HID + d];
    float4 n2 = *(const float4*)&n2w[(size_t)g * HID + d];

    float ssq = s0*s0 + s1*s1 + s2*s2 + s3*s3;
    float ksq = kv.x*kv.x + kv.y*kv.y + kv.z*kv.z + kv.w*kv.w;
    float dot = s0*kv.x*n1.x*n2.x + s1*kv.y*n1.y*n2.y
              + s2*kv.z*n1.z*n2.z + s3*kv.w*n1.w*n2.w;

    float3 red = block_reduce3(ssq, ksq, dot);

    float rq = rsqrtf(red.x * (1.f / HID) + 1e-6f);
    float rk = rsqrtf(red.y * (1.f / HID) + 1e-6f);
    float z  = red.z * rq * rk * (1.f / 32.f);
    float gate = 1.f / (1.f + __expf(-z));

    float4 vv = *(const float4*)&value[(size_t)bt * EMB + d];
    float4 o;
    o.x = gate * vv.x; o.y = gate * vv.y;
    o.z = gate * vv.z; o.w = gate * vv.w;
    *(float4*)&out[(size_t)r * HID + d] = o;
}

// ---------------------------------------------------------------------------
// Launch
// ---------------------------------------------------------------------------
extern "C" void kernel_launch(void* const* d_in, const int* in_sizes, int n_in,
                              void* d_out, int out_size) {
    const float* hidden = (const float*)d_in[0];
    const int*   hash   = (const int*)d_in[1];
    const float* tab    = (const float*)d_in[2];
    const float* convw  = (const float*)d_in[3];
    const float* scw    = (const float*)d_in[4];
    const float* vw     = (const float*)d_in[5];
    const float* vb     = (const float*)d_in[6];
    const float* kw     = (const float*)d_in[7];
    const float* kb     = (const float*)d_in[8];
    const float* n1     = (const float*)d_in[9];
    const float* n2     = (const float*)d_in[10];
    float* out = (float*)d_out;

    float *A, *val, *keys, *vwt, *kwt;
    cudaGetSymbolAddress((void**)&A,    g_A);
    cudaGetSymbolAddress((void**)&val,  g_value);
    cudaGetSymbolAddress((void**)&keys, g_keys);
    cudaGetSymbolAddress((void**)&vwt,  g_vwt);
    cudaGetSymbolAddress((void**)&kwt,  g_kwt);

    cudaFuncSetAttribute(gemm_tf32, cudaFuncAttributeMaxDynamicSharedMemorySize, TFB_SMEM);

    gather_k<<<BT, 256>>>(hash, tab, A);
    wround_k<<<(EMB * HID / 4 + 255) / 256, 256>>>(vw, vwt, EMB * HID / 4);
    wround_k<<<(CCH * HID / 4 + 255) / 256, 256>>>(kw, kwt, CCH * HID / 4);

    dim3 gv(EMB / 256, BT / 128);
    gemm_tf32<<<gv, 256, TFB_SMEM>>>(A, vwt, vb, val, EMB);

    dim3 gk(CCH / 256, BT / 128);
    gemm_tf32<<<gk, 256, TFB_SMEM>>>(A, kwt, kb, keys, CCH);

    final_k<<<BT * GDIM, 256>>>(hidden, scw, convw, keys, val, n1, n2, out);
}